// round 1
// baseline (speedup 1.0000x reference)
#include <cuda_runtime.h>

// Problem constants
#define NB   8
#define CC   256
#define HH   56
#define WWd  56
#define HWP  3136     // 56*56
#define PPAD 3200     // padded spatial dim: %16==0 for K, %128==0 for N tiles
#define K7   7
#define CKD  1792     // 256*7

// Scratch (device globals: allocation-free per harness rules)
__device__ float g_Xp[NB * CC * PPAD];     //  26 MB  x, zero-padded
__device__ float g_T5[NB * CKD * PPAD];    // 184 MB  t5 = t1 - t3
__device__ float g_T6[NB * CKD * PPAD];    // 184 MB  t6 = x + t4
__device__ float g_T7[NB * CC * CKD];      //  15 MB  scores

// ---------- packed f32x2 helpers (sm_103a FFMA2 path) ----------
__device__ __forceinline__ unsigned long long pack2(float lo, float hi) {
    unsigned long long r;
    asm("mov.b64 %0, {%1, %2};" : "=l"(r) : "f"(lo), "f"(hi));
    return r;
}
__device__ __forceinline__ void unpack2(unsigned long long v, float &lo, float &hi) {
    asm("mov.b64 {%0, %1}, %2;" : "=f"(lo), "=f"(hi) : "l"(v));
}
__device__ __forceinline__ void ffma2(unsigned long long &d, unsigned long long a,
                                      unsigned long long b) {
    asm("fma.rn.f32x2 %0, %1, %2, %0;" : "+l"(d) : "l"(a), "l"(b));
}

// ---------- prep: padded X copy ----------
__global__ void prep_xp_kernel(const float* __restrict__ x) {
    int idx = blockIdx.x * blockDim.x + threadIdx.x;
    if (idx >= NB * CC * PPAD) return;
    int p  = idx % PPAD;
    int nc = idx / PPAD;
    g_Xp[idx] = (p < HWP) ? x[nc * HWP + p] : 0.0f;
}

// ---------- prep: build T5, T6 ----------
// t1[j,p]     = p1w[j,p]*x[n,j,p]
// t2[j]       = t1[(j-1) mod C]                       (roll shift=+1 on channels)
// t3[j,k,h,w] = t2[j, h, w+k-3]  (zero pad in w)
// t4[j,k,h,w] = t3[j,k,(h-1)%H,(w+1)%W]              (roll +1 on h, -1 on w)
// T5 = t1 - t3 ;  T6 = x + t4
__global__ void prep_t56_kernel(const float* __restrict__ x, const float* __restrict__ p1w) {
    int idx = blockIdx.x * blockDim.x + threadIdx.x;
    if (idx >= NB * CKD * PPAD) return;
    int p = idx % PPAD;
    int t = idx / PPAD;
    int q = t % CKD;
    int n = t / CKD;
    if (p >= HWP) { g_T5[idx] = 0.0f; g_T6[idx] = 0.0f; return; }
    int j = q / K7, k = q % K7;
    int h = p / WWd, w = p % WWd;
    int jm = (j + CC - 1) % CC;
    const float* xn = x + n * CC * HWP;

    float t1 = p1w[j * HWP + p] * xn[j * HWP + p];

    int wk = w + k - 3;
    float t3 = 0.0f;
    if (wk >= 0 && wk < WWd) {
        int pp = h * WWd + wk;
        t3 = p1w[jm * HWP + pp] * xn[jm * HWP + pp];
    }
    int hh = (h + HH - 1) % HH;
    int w2 = (w + 1) % WWd;
    int wk2 = w2 + k - 3;
    float t4 = 0.0f;
    if (wk2 >= 0 && wk2 < WWd) {
        int pp = hh * WWd + wk2;
        t4 = p1w[jm * HWP + pp] * xn[jm * HWP + pp];
    }
    g_T5[idx] = t1 - t3;
    g_T6[idx] = xn[j * HWP + p] + t4;
}

// ---------- GEMM1 (NT): T7[n,i,q] = (1/56) * sum_p Xp[n,i,p] * T5[n,q,p] ----------
// M=256, N=1792, K=3200. 128x128 tile, 256 thr, 8x8/thread via f32x2 pairs along n.
__global__ __launch_bounds__(256, 2) void gemm1_nt_kernel() {
    const int lda = PPAD, ldb = PPAD, ldc = CKD;
    int z = blockIdx.z;
    const float* Ab = g_Xp + z * CC * PPAD + blockIdx.x * 128 * lda;
    const float* Bb = g_T5 + z * CKD * PPAD + blockIdx.y * 128 * ldb;
    float* Cb = g_T7 + z * CC * CKD + blockIdx.x * 128 * ldc + blockIdx.y * 128;

    int tid = threadIdx.x;
    int tx = tid & 15, ty = tid >> 4;
    int ar = tid >> 2;             // 0..63 tile row
    int akq = (tid & 3) << 2;      // 0,4,8,12 within BK

    __shared__ __align__(16) unsigned long long As2[16][128];  // duplicated (a,a)
    __shared__ __align__(16) float Bs[16][128];

    unsigned long long acc[8][4];
#pragma unroll
    for (int i = 0; i < 8; i++)
#pragma unroll
        for (int jj = 0; jj < 4; jj++) acc[i][jj] = 0ULL;

    const float* Aload = Ab + ar * lda + akq;
    const float* Bload = Bb + ar * ldb + akq;

    float4 pa0 = *(const float4*)(Aload);
    float4 pa1 = *(const float4*)(Aload + 64 * lda);
    float4 pb0 = *(const float4*)(Bload);
    float4 pb1 = *(const float4*)(Bload + 64 * ldb);

    const int KT = PPAD / 16;  // 200
    for (int kt = 0;; kt++) {
        As2[akq + 0][ar] = pack2(pa0.x, pa0.x);
        As2[akq + 1][ar] = pack2(pa0.y, pa0.y);
        As2[akq + 2][ar] = pack2(pa0.z, pa0.z);
        As2[akq + 3][ar] = pack2(pa0.w, pa0.w);
        As2[akq + 0][ar + 64] = pack2(pa1.x, pa1.x);
        As2[akq + 1][ar + 64] = pack2(pa1.y, pa1.y);
        As2[akq + 2][ar + 64] = pack2(pa1.z, pa1.z);
        As2[akq + 3][ar + 64] = pack2(pa1.w, pa1.w);
        Bs[akq + 0][ar] = pb0.x;
        Bs[akq + 1][ar] = pb0.y;
        Bs[akq + 2][ar] = pb0.z;
        Bs[akq + 3][ar] = pb0.w;
        Bs[akq + 0][ar + 64] = pb1.x;
        Bs[akq + 1][ar + 64] = pb1.y;
        Bs[akq + 2][ar + 64] = pb1.z;
        Bs[akq + 3][ar + 64] = pb1.w;
        __syncthreads();
        if (kt + 1 < KT) {
            int ko = (kt + 1) * 16;
            pa0 = *(const float4*)(Aload + ko);
            pa1 = *(const float4*)(Aload + 64 * lda + ko);
            pb0 = *(const float4*)(Bload + ko);
            pb1 = *(const float4*)(Bload + 64 * ldb + ko);
        }
#pragma unroll
        for (int k = 0; k < 16; k++) {
            ulonglong2 a01 = *(const ulonglong2*)&As2[k][ty * 8 + 0];
            ulonglong2 a23 = *(const ulonglong2*)&As2[k][ty * 8 + 2];
            ulonglong2 a45 = *(const ulonglong2*)&As2[k][ty * 8 + 4];
            ulonglong2 a67 = *(const ulonglong2*)&As2[k][ty * 8 + 6];
            ulonglong2 b01 = *(const ulonglong2*)&Bs[k][tx * 8 + 0];
            ulonglong2 b23 = *(const ulonglong2*)&Bs[k][tx * 8 + 4];
            unsigned long long aa[8] = {a01.x, a01.y, a23.x, a23.y,
                                        a45.x, a45.y, a67.x, a67.y};
            unsigned long long bb[4] = {b01.x, b01.y, b23.x, b23.y};
#pragma unroll
            for (int mi = 0; mi < 8; mi++)
#pragma unroll
                for (int nj = 0; nj < 4; nj++) ffma2(acc[mi][nj], aa[mi], bb[nj]);
        }
        if (kt + 1 >= KT) break;
        __syncthreads();
    }

    const float s = 1.0f / 56.0f;  // 1/sqrt(3136)
#pragma unroll
    for (int mi = 0; mi < 8; mi++) {
        float* crow = Cb + (ty * 8 + mi) * ldc + tx * 8;
#pragma unroll
        for (int nj = 0; nj < 4; nj++) {
            float lo, hi;
            unpack2(acc[mi][nj], lo, hi);
            *(float2*)(crow + nj * 2) = make_float2(lo * s, hi * s);
        }
    }
}

// ---------- GEMM2 (NN): out[n,i,p] = (1/sqrt(1792)) * sum_q T7[n,i,q] * T6[n,q,p] ----------
// M=256, N=3200 (store only p<3136), K=1792.
__global__ __launch_bounds__(256, 2) void gemm2_nn_kernel(float* __restrict__ out) {
    const int lda = CKD, ldb = PPAD, ldc = HWP;
    int z = blockIdx.z;
    const float* Ab = g_T7 + z * CC * CKD + blockIdx.x * 128 * lda;
    const float* Bb = g_T6 + z * CKD * PPAD + blockIdx.y * 128;
    float* Cb = out + z * CC * HWP + blockIdx.x * 128 * ldc + blockIdx.y * 128;

    int tid = threadIdx.x;
    int tx = tid & 15, ty = tid >> 4;
    int ar = tid >> 2;
    int akq = (tid & 3) << 2;
    int bk = tid >> 5;             // 0..7
    int bn = (tid & 31) << 2;      // 0..124

    __shared__ __align__(16) unsigned long long As2[16][128];
    __shared__ __align__(16) float Bs[16][128];

    unsigned long long acc[8][4];
#pragma unroll
    for (int i = 0; i < 8; i++)
#pragma unroll
        for (int jj = 0; jj < 4; jj++) acc[i][jj] = 0ULL;

    const float* Aload = Ab + ar * lda + akq;
    const float* Bload = Bb + bk * ldb + bn;

    float4 pa0 = *(const float4*)(Aload);
    float4 pa1 = *(const float4*)(Aload + 64 * lda);
    float4 pb0 = *(const float4*)(Bload);
    float4 pb1 = *(const float4*)(Bload + 8 * ldb);

    const int KT = CKD / 16;  // 112
    for (int kt = 0;; kt++) {
        As2[akq + 0][ar] = pack2(pa0.x, pa0.x);
        As2[akq + 1][ar] = pack2(pa0.y, pa0.y);
        As2[akq + 2][ar] = pack2(pa0.z, pa0.z);
        As2[akq + 3][ar] = pack2(pa0.w, pa0.w);
        As2[akq + 0][ar + 64] = pack2(pa1.x, pa1.x);
        As2[akq + 1][ar + 64] = pack2(pa1.y, pa1.y);
        As2[akq + 2][ar + 64] = pack2(pa1.z, pa1.z);
        As2[akq + 3][ar + 64] = pack2(pa1.w, pa1.w);
        *(float4*)&Bs[bk][bn] = pb0;
        *(float4*)&Bs[bk + 8][bn] = pb1;
        __syncthreads();
        if (kt + 1 < KT) {
            int ko = (kt + 1) * 16;
            pa0 = *(const float4*)(Aload + ko);
            pa1 = *(const float4*)(Aload + 64 * lda + ko);
            pb0 = *(const float4*)(Bload + ko * ldb);
            pb1 = *(const float4*)(Bload + (ko + 8) * ldb);
        }
#pragma unroll
        for (int k = 0; k < 16; k++) {
            ulonglong2 a01 = *(const ulonglong2*)&As2[k][ty * 8 + 0];
            ulonglong2 a23 = *(const ulonglong2*)&As2[k][ty * 8 + 2];
            ulonglong2 a45 = *(const ulonglong2*)&As2[k][ty * 8 + 4];
            ulonglong2 a67 = *(const ulonglong2*)&As2[k][ty * 8 + 6];
            ulonglong2 b01 = *(const ulonglong2*)&Bs[k][tx * 8 + 0];
            ulonglong2 b23 = *(const ulonglong2*)&Bs[k][tx * 8 + 4];
            unsigned long long aa[8] = {a01.x, a01.y, a23.x, a23.y,
                                        a45.x, a45.y, a67.x, a67.y};
            unsigned long long bb[4] = {b01.x, b01.y, b23.x, b23.y};
#pragma unroll
            for (int mi = 0; mi < 8; mi++)
#pragma unroll
                for (int nj = 0; nj < 4; nj++) ffma2(acc[mi][nj], aa[mi], bb[nj]);
        }
        if (kt + 1 >= KT) break;
        __syncthreads();
    }

    const float s = 0.0236227795f;  // 1/sqrt(1792)
    int ncol0 = blockIdx.y * 128 + tx * 8;
#pragma unroll
    for (int mi = 0; mi < 8; mi++) {
        float* crow = Cb + (ty * 8 + mi) * ldc + tx * 8;
#pragma unroll
        for (int nj = 0; nj < 4; nj++) {
            if (ncol0 + nj * 2 < HWP) {
                float lo, hi;
                unpack2(acc[mi][nj], lo, hi);
                *(float2*)(crow + nj * 2) = make_float2(lo * s, hi * s);
            }
        }
    }
}

extern "C" void kernel_launch(void* const* d_in, const int* in_sizes, int n_in,
                              void* d_out, int out_size) {
    (void)in_sizes; (void)n_in; (void)out_size;
    const float* x   = (const float*)d_in[0];
    const float* p1w = (const float*)d_in[1];
    float* out = (float*)d_out;

    {
        int total = NB * CC * PPAD;
        prep_xp_kernel<<<(total + 255) / 256, 256>>>(x);
    }
    {
        int total = NB * CKD * PPAD;
        prep_t56_kernel<<<(total + 255) / 256, 256>>>(x, p1w);
    }
    gemm1_nt_kernel<<<dim3(CC / 128, CKD / 128, NB), 256>>>();
    gemm2_nn_kernel<<<dim3(CC / 128, PPAD / 128, NB), 256>>>(out);
}

// round 4
// speedup vs baseline: 2.4161x; 2.4161x over previous
#include <cuda_runtime.h>
#include <cstdint>

#define NB   8
#define CC   256
#define HH   56
#define WWd  56
#define HWP  3136
#define PPAD 3200
#define K7   7
#define CKD  1792

// Scratch
__device__ float g_Xp [NB * CC  * PPAD];   //  26 MB  A1: x zero-padded, tf32-rounded
__device__ float g_T5 [NB * CKD * PPAD];   // 184 MB  B1: t5, K-major (p contiguous)
__device__ float g_T6t[NB * PPAD * CKD];   // 184 MB  B2: t6 transposed [p, q] (q contiguous)
__device__ float g_T7 [NB * CC  * CKD];    //  15 MB  A2: scores, K-major (q contiguous)

__device__ __forceinline__ uint32_t smem_u32(const void* p) {
    uint32_t a;
    asm("{ .reg .u64 t; cvta.to.shared.u64 t, %1; cvt.u32.u64 %0, t; }" : "=r"(a) : "l"(p));
    return a;
}
__device__ __forceinline__ float rna_tf32(float x) {
    uint32_t r;
    asm("cvt.rna.tf32.f32 %0, %1;" : "=r"(r) : "f"(x));
    return __uint_as_float(r);
}
__device__ __forceinline__ uint32_t lds32(uint32_t a) {
    uint32_t v;
    asm volatile("ld.shared.b32 %0, [%1];" : "=r"(v) : "r"(a));
    return v;
}
#define CP_ASYNC16(dst, src) \
    asm volatile("cp.async.cg.shared.global [%0], [%1], 16;" :: "r"(dst), "l"(src))
#define CP_COMMIT() asm volatile("cp.async.commit_group;")
#define CP_WAIT2()  asm volatile("cp.async.wait_group 2;" ::: "memory")

// ---------------- prep kernels ----------------
__global__ void prep_xp_kernel(const float* __restrict__ x) {
    int idx = blockIdx.x * blockDim.x + threadIdx.x;
    if (idx >= NB * CC * PPAD) return;
    int p  = idx % PPAD;
    int nc = idx / PPAD;
    g_Xp[idx] = (p < HWP) ? rna_tf32(x[nc * HWP + p]) : 0.0f;
}

// T5[n,q,p] = t1[j,p] - t3[j,k,p]
__global__ void prep_t5_kernel(const float* __restrict__ x, const float* __restrict__ p1w) {
    int idx = blockIdx.x * blockDim.x + threadIdx.x;
    if (idx >= NB * CKD * PPAD) return;
    int p = idx % PPAD;
    int t = idx / PPAD;
    int q = t % CKD;
    int n = t / CKD;
    if (p >= HWP) { g_T5[idx] = 0.0f; return; }
    int j = q / K7, k = q % K7;
    int h = p / WWd, w = p % WWd;
    int jm = (j + CC - 1) % CC;
    const float* xn = x + n * CC * HWP;

    float t1 = p1w[j * HWP + p] * xn[j * HWP + p];
    int wk = w + k - 3;
    float t3 = 0.0f;
    if (wk >= 0 && wk < WWd) {
        int pp = h * WWd + wk;
        t3 = p1w[jm * HWP + pp] * xn[jm * HWP + pp];
    }
    g_T5[idx] = rna_tf32(t1 - t3);
}

// T6t[n,p,q] = x[n,j,p] + t4[j,k,p]   (q contiguous)
__global__ __launch_bounds__(256) void prep_t6t_kernel(const float* __restrict__ x,
                                                       const float* __restrict__ p1w) {
    __shared__ float ts[64][33];
    int p0 = blockIdx.x * 32;
    int q0 = blockIdx.y * 64;
    int n  = blockIdx.z;
    int t  = threadIdx.x;
    int tp = t & 31;
    int tq = t >> 5;

    const float* xn = x + n * CC * HWP;
    int p = p0 + tp;
    bool pv = (p < HWP);
    int h = p / WWd, w = p % WWd;
    int hh = (h + HH - 1) % HH;
    int w2 = (w + 1) % WWd;

#pragma unroll
    for (int qi = 0; qi < 8; qi++) {
        int ql = tq + 8 * qi;
        int q = q0 + ql;
        float val = 0.0f;
        if (pv) {
            int j = q / K7, k = q % K7;
            int jm = (j + CC - 1) % CC;
            float t4 = 0.0f;
            int wk2 = w2 + k - 3;
            if (wk2 >= 0 && wk2 < WWd) {
                int pp = hh * WWd + wk2;
                t4 = p1w[jm * HWP + pp] * xn[jm * HWP + pp];
            }
            val = rna_tf32(xn[j * HWP + p] + t4);
        }
        ts[ql][tp] = val;
    }
    __syncthreads();

    int ql = t & 63;
    int pl = t >> 6;
    float* dst = g_T6t + ((long)n * PPAD) * CKD;
#pragma unroll
    for (int pi = 0; pi < 8; pi++) {
        int prow = p0 + pl + 4 * pi;
        dst[(long)prow * CKD + q0 + ql] = ts[ql][pl + 4 * pi];
    }
}

// ---------------- TF32 mma.sync GEMM (NT): C = scale * A(MxK) * B(NxK)^T ----------------
// Block 128x128xBK32, 256 thr, 8 warps (2 m x 4 n), warp 64x32 = 4x4 m16n8k8 frags.
// Smem: SW128 swizzle -> element (m,k) at m*128 + ((4k) ^ ((m&7)<<4)); conflict-free LDS.32.
__global__ __launch_bounds__(256, 1)
void gemm_mma(const float* __restrict__ A, const float* __restrict__ B, float* __restrict__ C,
              int K, int KT, long sAz, long sBz, long sCz, int ldc, float scale,
              int nvalid, int round_out) {
    extern __shared__ __align__(1024) char smem[];
    const uint32_t STGB = 32768;   // 16KB A + 16KB B
    uint32_t sb = smem_u32(smem);

    int tid = threadIdx.x, lane = tid & 31, wid = tid >> 5;
    int g = lane >> 2, t = lane & 3;
    int mwarp = (wid & 1) * 64, nwarp = (wid >> 1) * 32;

    const float* Ab = A + (long)blockIdx.z * sAz + (long)(blockIdx.x * 128) * K;
    const float* Bb = B + (long)blockIdx.z * sBz + (long)(blockIdx.y * 128) * K;

    // staging: thread -> row tid>>1, granules gr0..gr0+3 (64B)
    int srow = tid >> 1;
    int gr0 = (tid & 1) * 4;
    const char* aSrc = (const char*)(Ab + (long)srow * K) + gr0 * 16;
    const char* bSrc = (const char*)(Bb + (long)srow * K) + gr0 * 16;
    uint32_t aDst = sb + srow * 128;
    uint32_t bDst = sb + 16384 + srow * 128;
    uint32_t swz = (srow & 7) * 16;

    float c[4][4][4];
#pragma unroll
    for (int mi = 0; mi < 4; mi++)
#pragma unroll
        for (int ni = 0; ni < 4; ni++)
#pragma unroll
            for (int e = 0; e < 4; e++) c[mi][ni][e] = 0.0f;

    // prologue: stages 0..2
#pragma unroll
    for (int s = 0; s < 3; s++) {
        uint32_t st = s * STGB;
        long go = (long)s * 128;
#pragma unroll
        for (int j = 0; j < 4; j++) {
            uint32_t off = (uint32_t)(((gr0 + j) * 16) ^ swz);
            CP_ASYNC16(aDst + st + off, aSrc + go + j * 16);
            CP_ASYNC16(bDst + st + off, bSrc + go + j * 16);
        }
        CP_COMMIT();
    }

#pragma unroll 1
    for (int kt = 0; kt < KT; kt++) {
        CP_WAIT2();
        __syncthreads();
        // issue stage kt+3 (or empty commit to keep group numbering)
        if (kt + 3 < KT) {
            uint32_t st = ((kt + 3) & 3) * STGB;
            long go = (long)(kt + 3) * 128;
#pragma unroll
            for (int j = 0; j < 4; j++) {
                uint32_t off = (uint32_t)(((gr0 + j) * 16) ^ swz);
                CP_ASYNC16(aDst + st + off, aSrc + go + j * 16);
                CP_ASYNC16(bDst + st + off, bSrc + go + j * 16);
            }
        }
        CP_COMMIT();

        uint32_t sA = sb + (kt & 3) * STGB;
        uint32_t sB = sA + 16384;
#pragma unroll
        for (int kk = 0; kk < 4; kk++) {
            int k0 = kk * 8;
            uint32_t kx1 = (uint32_t)(((k0 + t) * 4) ^ (g << 4));
            uint32_t kx2 = (uint32_t)(((k0 + t + 4) * 4) ^ (g << 4));
            uint32_t a[4][4];
#pragma unroll
            for (int mi = 0; mi < 4; mi++) {
                uint32_t b0 = sA + (uint32_t)((mwarp + mi * 16 + g) * 128);
                uint32_t b1 = b0 + 8 * 128;
                a[mi][0] = lds32(b0 + kx1);
                a[mi][1] = lds32(b1 + kx1);
                a[mi][2] = lds32(b0 + kx2);
                a[mi][3] = lds32(b1 + kx2);
            }
            uint32_t b[4][2];
#pragma unroll
            for (int ni = 0; ni < 4; ni++) {
                uint32_t nb = sB + (uint32_t)((nwarp + ni * 8 + g) * 128);
                b[ni][0] = lds32(nb + kx1);
                b[ni][1] = lds32(nb + kx2);
            }
#pragma unroll
            for (int mi = 0; mi < 4; mi++)
#pragma unroll
                for (int ni = 0; ni < 4; ni++) {
                    asm volatile(
                        "mma.sync.aligned.m16n8k8.row.col.f32.tf32.tf32.f32 "
                        "{%0,%1,%2,%3}, {%4,%5,%6,%7}, {%8,%9}, {%0,%1,%2,%3};"
                        : "+f"(c[mi][ni][0]), "+f"(c[mi][ni][1]),
                          "+f"(c[mi][ni][2]), "+f"(c[mi][ni][3])
                        : "r"(a[mi][0]), "r"(a[mi][1]), "r"(a[mi][2]), "r"(a[mi][3]),
                          "r"(b[ni][0]), "r"(b[ni][1]));
                }
        }
    }

    // epilogue
    float* Cz = C + (long)blockIdx.z * sCz;
    int colbase = blockIdx.y * 128 + nwarp;
#pragma unroll
    for (int mi = 0; mi < 4; mi++) {
        int row0 = blockIdx.x * 128 + mwarp + mi * 16 + g;
        int row1 = row0 + 8;
#pragma unroll
        for (int ni = 0; ni < 4; ni++) {
            int col = colbase + ni * 8 + 2 * t;
            if (col < nvalid) {
                float2 v0, v1;
                v0.x = c[mi][ni][0] * scale; v0.y = c[mi][ni][1] * scale;
                v1.x = c[mi][ni][2] * scale; v1.y = c[mi][ni][3] * scale;
                if (round_out) {
                    v0.x = rna_tf32(v0.x); v0.y = rna_tf32(v0.y);
                    v1.x = rna_tf32(v1.x); v1.y = rna_tf32(v1.y);
                }
                *(float2*)(Cz + (long)row0 * ldc + col) = v0;
                *(float2*)(Cz + (long)row1 * ldc + col) = v1;
            }
        }
    }
}

// ---------------- launch ----------------
extern "C" void kernel_launch(void* const* d_in, const int* in_sizes, int n_in,
                              void* d_out, int out_size) {
    (void)in_sizes; (void)n_in; (void)out_size;
    const float* x   = (const float*)d_in[0];
    const float* p1w = (const float*)d_in[1];
    float* out = (float*)d_out;

    const int SMEM = 4 * 32768;  // 128 KB
    cudaFuncSetAttribute(gemm_mma, cudaFuncAttributeMaxDynamicSharedMemorySize, SMEM);

    {
        int total = NB * CC * PPAD;
        prep_xp_kernel<<<(total + 255) / 256, 256>>>(x);
    }
    {
        int total = NB * CKD * PPAD;
        prep_t5_kernel<<<(total + 255) / 256, 256>>>(x, p1w);
    }
    prep_t6t_kernel<<<dim3(PPAD / 32, CKD / 64, NB), 256>>>(x, p1w);

    float *T7, *Xp, *T5, *T6t;
    cudaGetSymbolAddress((void**)&T7,  g_T7);
    cudaGetSymbolAddress((void**)&Xp,  g_Xp);
    cudaGetSymbolAddress((void**)&T5,  g_T5);
    cudaGetSymbolAddress((void**)&T6t, g_T6t);

    // GEMM1: T7[i,q] = (1/56) * sum_p Xp[i,p]*T5[q,p];  M=256,N=1792,K=3200
    gemm_mma<<<dim3(CC / 128, CKD / 128, NB), 256, SMEM>>>(
        Xp, T5, T7, PPAD, PPAD / 32,
        (long)CC * PPAD, (long)CKD * PPAD, (long)CC * CKD,
        CKD, 1.0f / 56.0f, CKD, 1);

    // GEMM2: out[i,p] = (1/sqrt(1792)) * sum_q T7[i,q]*T6t[p,q];  M=256,N=3200,K=1792
    gemm_mma<<<dim3(CC / 128, PPAD / 128, NB), 256, SMEM>>>(
        T7, T6t, out, CKD, CKD / 32,
        (long)CC * CKD, (long)PPAD * CKD, (long)CC * HWP,
        HWP, 0.0236227795f, HWP, 0);
}

// round 5
// speedup vs baseline: 2.4732x; 1.0236x over previous
#include <cuda_runtime.h>
#include <cstdint>

#define NB   8
#define CC   256
#define HH   56
#define WWd  56
#define HWP  3136
#define PPAD 3200
#define K7   7
#define CKD  1792

// Scratch
__device__ float g_Xp [NB * CC  * PPAD];   //  26 MB  A1
__device__ float g_T5 [NB * CKD * PPAD];   // 184 MB  B1 (p contiguous)
__device__ float g_T6t[NB * PPAD * CKD];   // 184 MB  B2 transposed (q contiguous)
__device__ float g_T7 [NB * CC  * CKD];    //  15 MB  A2 (q contiguous)

__device__ __forceinline__ uint32_t smem_u32(const void* p) {
    uint32_t a;
    asm("{ .reg .u64 t; cvta.to.shared.u64 t, %1; cvt.u32.u64 %0, t; }" : "=r"(a) : "l"(p));
    return a;
}
__device__ __forceinline__ float rna_tf32(float x) {
    uint32_t r;
    asm("cvt.rna.tf32.f32 %0, %1;" : "=r"(r) : "f"(x));
    return __uint_as_float(r);
}
__device__ __forceinline__ uint32_t lds32(uint32_t a) {
    uint32_t v;
    asm volatile("ld.shared.b32 %0, [%1];" : "=r"(v) : "r"(a));
    return v;
}
#define CP_ASYNC16(dst, src) \
    asm volatile("cp.async.cg.shared.global [%0], [%1], 16;" :: "r"(dst), "l"(src))
#define CP_COMMIT() asm volatile("cp.async.commit_group;")
#define CP_WAIT2()  asm volatile("cp.async.wait_group 2;" ::: "memory")

// ---------------- prep ----------------
__global__ void prep_xp_kernel(const float* __restrict__ x) {
    int idx = blockIdx.x * blockDim.x + threadIdx.x;
    if (idx >= NB * CC * PPAD) return;
    int p  = idx % PPAD;
    int nc = idx / PPAD;
    g_Xp[idx] = (p < HWP) ? rna_tf32(x[nc * HWP + p]) : 0.0f;
}

// Fused: writes T5[n,q,p] (p-contiguous) and T6t[n,p,q] (q-contiguous, via smem transpose)
__global__ __launch_bounds__(256) void prep_t56_kernel(const float* __restrict__ x,
                                                       const float* __restrict__ p1w) {
    __shared__ float ts[64][33];
    int p0 = blockIdx.x * 32;         // 100 tiles over PPAD
    int q0 = blockIdx.y * 64;         // 28 tiles over CKD
    int n  = blockIdx.z;
    int t  = threadIdx.x;
    int tp = t & 31;
    int tq = t >> 5;

    const float* xn = x + n * CC * HWP;
    int p = p0 + tp;
    bool pv = (p < HWP);
    int h = p / WWd, w = p % WWd;
    int hh = (h + HH - 1) % HH;
    int w2 = (w + 1) % WWd;
    float* t5n = g_T5 + ((long)n * CKD) * PPAD;

#pragma unroll
    for (int qi = 0; qi < 8; qi++) {
        int ql = tq + 8 * qi;
        int q = q0 + ql;
        float v5 = 0.0f, v6 = 0.0f;
        if (pv) {
            int j = q / K7, k = q % K7;
            int jm = (j + CC - 1) % CC;
            float xv  = xn[j * HWP + p];
            float t1  = p1w[j * HWP + p] * xv;
            float t3 = 0.0f;
            int wk = w + k - 3;
            if (wk >= 0 && wk < WWd) {
                int pp = h * WWd + wk;
                t3 = p1w[jm * HWP + pp] * xn[jm * HWP + pp];
            }
            float t4 = 0.0f;
            int wk2 = w2 + k - 3;
            if (wk2 >= 0 && wk2 < WWd) {
                int pp = hh * WWd + wk2;
                t4 = p1w[jm * HWP + pp] * xn[jm * HWP + pp];
            }
            v5 = rna_tf32(t1 - t3);
            v6 = rna_tf32(xv + t4);
        }
        t5n[(long)q * PPAD + p] = v5;   // coalesced over tp
        ts[ql][tp] = v6;
    }
    __syncthreads();

    int ql = t & 63;
    int pl = t >> 6;
    float* dst = g_T6t + ((long)n * PPAD) * CKD;
#pragma unroll
    for (int pi = 0; pi < 8; pi++) {
        int prow = p0 + pl + 4 * pi;
        dst[(long)prow * CKD + q0 + ql] = ts[ql][pl + 4 * pi];
    }
}

// ---------------- TF32 mma.sync GEMM (NT): C = scale * A(MxK) * B(NxK)^T ----------------
// Block 256x128xBK32, 256 thr, 8 warps (4m x 2n), warp tile 64x64 = 4x8 m16n8k8 frags.
// Smem elem (row,k) at row*128 + ((k*4) ^ ((row&7)<<4)): conflict-free LDS.32 frags.
__global__ __launch_bounds__(256)
void gemm_mma(const float* __restrict__ A, const float* __restrict__ B, float* __restrict__ C,
              int K, int KT, long sAz, long sBz, long sCz, int ldc, float scale,
              int nvalid, int round_out) {
    extern __shared__ __align__(1024) char smem[];
    const uint32_t STGB = 49152;   // 32KB A + 16KB B per stage
    uint32_t sb = smem_u32(smem);

    int tid = threadIdx.x, lane = tid & 31, wid = tid >> 5;
    int g = lane >> 2, t = lane & 3;
    int mwarp = (wid & 3) * 64, nwarp = (wid >> 2) * 64;

    const float* Ab = A + (long)blockIdx.z * sAz;                       // 256 rows
    const float* Bb = B + (long)blockIdx.z * sBz + (long)(blockIdx.y * 128) * K;

    // staging: A row tid (8 granules), B row tid>>1 (4 granules)
    const char* aSrc = (const char*)(Ab + (long)tid * K);
    uint32_t aDst = sb + tid * 128;
    uint32_t aswz = (tid & 7) * 16;
    int bsrow = tid >> 1;
    int bgr0 = (tid & 1) * 4;
    const char* bSrc = (const char*)(Bb + (long)bsrow * K) + bgr0 * 16;
    uint32_t bDst = sb + 32768 + bsrow * 128;
    uint32_t bswz = (bsrow & 7) * 16;

    float c[4][8][4];
#pragma unroll
    for (int mi = 0; mi < 4; mi++)
#pragma unroll
        for (int ni = 0; ni < 8; ni++)
#pragma unroll
            for (int e = 0; e < 4; e++) c[mi][ni][e] = 0.0f;

    // prologue: stages 0..2
#pragma unroll
    for (int s = 0; s < 3; s++) {
        uint32_t st = s * STGB;
        long go = (long)s * 128;
#pragma unroll
        for (int j = 0; j < 8; j++)
            CP_ASYNC16(aDst + st + (uint32_t)((j * 16) ^ aswz), aSrc + go + j * 16);
#pragma unroll
        for (int j = 0; j < 4; j++)
            CP_ASYNC16(bDst + st + (uint32_t)((((bgr0 + j) * 16) ^ bswz)), bSrc + go + j * 16);
        CP_COMMIT();
    }

#pragma unroll 1
    for (int kt = 0; kt < KT; kt++) {
        CP_WAIT2();
        __syncthreads();
        if (kt + 3 < KT) {
            uint32_t st = ((kt + 3) & 3) * STGB;
            long go = (long)(kt + 3) * 128;
#pragma unroll
            for (int j = 0; j < 8; j++)
                CP_ASYNC16(aDst + st + (uint32_t)((j * 16) ^ aswz), aSrc + go + j * 16);
#pragma unroll
            for (int j = 0; j < 4; j++)
                CP_ASYNC16(bDst + st + (uint32_t)((((bgr0 + j) * 16) ^ bswz)), bSrc + go + j * 16);
        }
        CP_COMMIT();

        uint32_t sA = sb + (kt & 3) * STGB;
        uint32_t sB = sA + 32768;
#pragma unroll
        for (int kk = 0; kk < 4; kk++) {
            int k0 = kk * 8;
            uint32_t kx1 = (uint32_t)(((k0 + t) * 4) ^ (g << 4));
            uint32_t kx2 = (uint32_t)(((k0 + t + 4) * 4) ^ (g << 4));
            uint32_t a[4][4];
#pragma unroll
            for (int mi = 0; mi < 4; mi++) {
                uint32_t b0 = sA + (uint32_t)((mwarp + mi * 16 + g) * 128);
                uint32_t b1 = b0 + 8 * 128;
                a[mi][0] = lds32(b0 + kx1);
                a[mi][1] = lds32(b1 + kx1);
                a[mi][2] = lds32(b0 + kx2);
                a[mi][3] = lds32(b1 + kx2);
            }
            uint32_t b[8][2];
#pragma unroll
            for (int ni = 0; ni < 8; ni++) {
                uint32_t nb = sB + (uint32_t)((nwarp + ni * 8 + g) * 128);
                b[ni][0] = lds32(nb + kx1);
                b[ni][1] = lds32(nb + kx2);
            }
#pragma unroll
            for (int mi = 0; mi < 4; mi++)
#pragma unroll
                for (int ni = 0; ni < 8; ni++) {
                    asm volatile(
                        "mma.sync.aligned.m16n8k8.row.col.f32.tf32.tf32.f32 "
                        "{%0,%1,%2,%3}, {%4,%5,%6,%7}, {%8,%9}, {%0,%1,%2,%3};"
                        : "+f"(c[mi][ni][0]), "+f"(c[mi][ni][1]),
                          "+f"(c[mi][ni][2]), "+f"(c[mi][ni][3])
                        : "r"(a[mi][0]), "r"(a[mi][1]), "r"(a[mi][2]), "r"(a[mi][3]),
                          "r"(b[ni][0]), "r"(b[ni][1]));
                }
        }
    }

    // epilogue
    float* Cz = C + (long)blockIdx.z * sCz;
    int colbase = blockIdx.y * 128 + nwarp;
#pragma unroll
    for (int mi = 0; mi < 4; mi++) {
        int row0 = mwarp + mi * 16 + g;
        int row1 = row0 + 8;
#pragma unroll
        for (int ni = 0; ni < 8; ni++) {
            int col = colbase + ni * 8 + 2 * t;
            if (col < nvalid) {
                float2 v0, v1;
                v0.x = c[mi][ni][0] * scale; v0.y = c[mi][ni][1] * scale;
                v1.x = c[mi][ni][2] * scale; v1.y = c[mi][ni][3] * scale;
                if (round_out) {
                    v0.x = rna_tf32(v0.x); v0.y = rna_tf32(v0.y);
                    v1.x = rna_tf32(v1.x); v1.y = rna_tf32(v1.y);
                }
                *(float2*)(Cz + (long)row0 * ldc + col) = v0;
                *(float2*)(Cz + (long)row1 * ldc + col) = v1;
            }
        }
    }
}

// ---------------- launch ----------------
extern "C" void kernel_launch(void* const* d_in, const int* in_sizes, int n_in,
                              void* d_out, int out_size) {
    (void)in_sizes; (void)n_in; (void)out_size;
    const float* x   = (const float*)d_in[0];
    const float* p1w = (const float*)d_in[1];
    float* out = (float*)d_out;

    const int SMEM = 4 * 49152;  // 192 KB
    cudaFuncSetAttribute(gemm_mma, cudaFuncAttributeMaxDynamicSharedMemorySize, SMEM);

    {
        int total = NB * CC * PPAD;
        prep_xp_kernel<<<(total + 255) / 256, 256>>>(x);
    }
    prep_t56_kernel<<<dim3(PPAD / 32, CKD / 64, NB), 256>>>(x, p1w);

    float *T7, *Xp, *T5, *T6t;
    cudaGetSymbolAddress((void**)&T7,  g_T7);
    cudaGetSymbolAddress((void**)&Xp,  g_Xp);
    cudaGetSymbolAddress((void**)&T5,  g_T5);
    cudaGetSymbolAddress((void**)&T6t, g_T6t);

    // GEMM1: T7[i,q] = (1/56) * sum_p Xp[i,p]*T5[q,p];  M=256,N=1792,K=3200
    gemm_mma<<<dim3(1, CKD / 128, NB), 256, SMEM>>>(
        Xp, T5, T7, PPAD, PPAD / 32,
        (long)CC * PPAD, (long)CKD * PPAD, (long)CC * CKD,
        CKD, 1.0f / 56.0f, CKD, 1);

    // GEMM2: out[i,p] = (1/sqrt(1792)) * sum_q T7[i,q]*T6t[p,q];  M=256,N=3200,K=1792
    gemm_mma<<<dim3(1, PPAD / 128, NB), 256, SMEM>>>(
        T7, T6t, out, CKD, CKD / 32,
        (long)CC * CKD, (long)PPAD * CKD, (long)CC * HWP,
        HWP, 0.0236227795f, HWP, 0);
}